// round 17
// baseline (speedup 1.0000x reference)
#include <cuda_runtime.h>
#include <cuda_bf16.h>
#include <cstdint>

#define NN 100000
#define EE 1600000
#define D  128
#define OD 64
#define NG 512
#define SCAN_BLK 512
#define NBLK ((NN + SCAN_BLK - 1) / SCAN_BLK)   // 196

// Scratch (device globals: allocation-free)
__device__ __align__(16) __nv_bfloat16 g_bufA1[NN * D]; // layer-1 messages
__device__ __align__(16) __nv_bfloat16 g_bufA2[NN * D]; // layer-2 messages
__device__ __align__(16) __nv_bfloat16 g_Ahi[NN * D];   // GEMM A input (hi only)
__device__ float g_dinv[NN];
__device__ __align__(16) float g_pool[NG * D];   // zeroed by k_final (self-clean)
__device__ int   g_cnt[NN];                      // zeroed by k_scan (self-clean)
__device__ int   g_pos[NN];
__device__ int   g_rowptr[NN + 1];
__device__ unsigned long long g_state[NBLK];     // lookback state; zeroed by k_fill
__device__ int   g_csr[EE];
// Pre-transposed, bf16-split weights: [n*128 + k]  (B side MUST stay split:
// weight rounding is coherent across the pool; A-side rounding washes out)
__device__ __align__(16) __nv_bfloat16 g_W1hi[D * D];
__device__ __align__(16) __nv_bfloat16 g_W1lo[D * D];
__device__ __align__(16) __nv_bfloat16 g_W2hi[D * D];
__device__ __align__(16) __nv_bfloat16 g_W2lo[D * D];

__device__ __forceinline__ void red_add_v4(float* addr, float4 v) {
    asm volatile("red.global.add.v4.f32 [%0], {%1,%2,%3,%4};"
                 :: "l"(__cvta_generic_to_global(addr)),
                    "f"(v.x), "f"(v.y), "f"(v.z), "f"(v.w)
                 : "memory");
}

__device__ __forceinline__ uint32_t pack_bf2(float a, float b) {
    __nv_bfloat162 t = __floats2bfloat162_rn(a, b);
    return *reinterpret_cast<uint32_t*>(&t);
}

// ---------------------------------------------------------------------------
__global__ void k_count(const int* __restrict__ ei) {
    int i = blockIdx.x * blockDim.x + threadIdx.x;
    if (i < EE) atomicAdd(&g_cnt[ei[EE + i]], 1);
}

#define NB_PREPX ((NN * D / 4 + 255) / 256)  // 12500
#define NB_PREPW 128

__global__ void k_prepxw(const float* __restrict__ x,
                         const float* __restrict__ W1, const float* __restrict__ W2) {
    int b = blockIdx.x;
    if (b < NB_PREPX) {
        int i = b * 256 + threadIdx.x;   // float4 index
        if (i < NN * D / 4) {
            float4 v = reinterpret_cast<const float4*>(x)[i];
            reinterpret_cast<uint2*>(g_Ahi)[i] =
                make_uint2(pack_bf2(v.x, v.y), pack_bf2(v.z, v.w));
        }
    } else {
        int id = (b - NB_PREPX) * 256 + threadIdx.x;   // 0..32767
        int w = id >> 14;
        int r = id & 16383;
        int k = r >> 7, n = r & 127;
        float v = (w ? W2 : W1)[k * D + n];
        __nv_bfloat16 hi = __float2bfloat16_rn(v);
        __nv_bfloat16 lo = __float2bfloat16_rn(v - __bfloat162float(hi));
        (w ? g_W2hi : g_W1hi)[n * D + k] = hi;
        (w ? g_W2lo : g_W1lo)[n * D + k] = lo;
    }
}

// ---------------------------------------------------------------------------
// Single-pass decoupled-lookback scan + rowptr/cursors/dinv epilogue.
__global__ void k_scan() {
    __shared__ int s[SCAN_BLK];
    __shared__ int s_pref;
    const int t = threadIdx.x, b = blockIdx.x;
    int gid = b * SCAN_BLK + t;
    int cnt = (gid < NN) ? g_cnt[gid] : 0;
    s[t] = cnt;
    __syncthreads();
    #pragma unroll
    for (int off = 1; off < SCAN_BLK; off <<= 1) {
        int v = (t >= off) ? s[t - off] : 0;
        __syncthreads();
        s[t] += v;
        __syncthreads();
    }
    int incl_local = s[t];
    int bsum = s[SCAN_BLK - 1];

    if (t == 0) {
        unsigned long long pub = (b == 0)
            ? ((2ULL << 32) | (unsigned)bsum)
            : ((1ULL << 32) | (unsigned)bsum);
        asm volatile("st.volatile.global.u64 [%0], %1;"
                     :: "l"(&g_state[b]), "l"(pub) : "memory");
        if (b == 0) s_pref = 0;
    }
    if (b > 0 && t < 32) {
        int excl = 0;
        int idx = b - 1 - t;   // lane 0 = nearest predecessor
        for (;;) {
            unsigned long long v = 0;
            if (idx >= 0) {
                do {
                    asm volatile("ld.volatile.global.u64 %0, [%1];"
                                 : "=l"(v) : "l"(&g_state[idx]));
                } while ((unsigned)(v >> 32) == 0u);
            }
            unsigned st = (idx >= 0) ? (unsigned)(v >> 32) : 0u;
            int val = (int)(unsigned)(v & 0xffffffffu);
            unsigned pm = __ballot_sync(0xffffffffu, st == 2u);
            int contrib;
            bool done;
            if (pm) {
                int leader = __ffs(pm) - 1;
                contrib = (t <= leader) ? val : 0;
                done = true;
            } else {
                contrib = (st != 0u) ? val : 0;
                done = false;
            }
            #pragma unroll
            for (int o = 16; o; o >>= 1)
                contrib += __shfl_down_sync(0xffffffffu, contrib, o);
            if (t == 0) excl += contrib;
            if (done) break;
            idx -= 32;
        }
        if (t == 0) {
            unsigned long long pub = (2ULL << 32) | (unsigned)(excl + bsum);
            asm volatile("st.volatile.global.u64 [%0], %1;"
                         :: "l"(&g_state[b]), "l"(pub) : "memory");
            s_pref = excl;
        }
    }
    __syncthreads();
    int pref = s_pref;
    if (gid < NN) {
        int incl = incl_local + pref;
        g_rowptr[gid + 1] = incl;
        g_cnt[gid] = 0;                          // self-clean for next replay
        g_pos[gid] = incl - cnt;
        g_dinv[gid] = rsqrtf((float)(cnt + 1));
    }
    if (gid == 0) g_rowptr[0] = 0;
}

__global__ void k_fill(const int* __restrict__ ei) {
    int i = blockIdx.x * blockDim.x + threadIdx.x;
    if (i < NBLK) g_state[i] = 0ull;             // self-clean scan state
    if (i < EE) {
        int s = ei[i];
        int d = ei[EE + i];
        g_csr[atomicAdd(&g_pos[d], 1)] = s;
    }
}

// ---------------------------------------------------------------------------
// Split-bf16 GEMM, A = hi only, two-stage cp.async pipeline:
// stage chunk0 (48KB) | stage chunk1 | compute0 (overlaps chunk1 load) | compute1.
#define SWZ(x) ((x) ^ (((x) >> 3) & 0x70))
#define S_AHI 0
#define S_BHI 32768
#define S_BLO 65536
#define GEMM_SMEM 98304

__device__ __forceinline__ void cp16(uint32_t dst, const void* src, int srcsize) {
    asm volatile("cp.async.cg.shared.global [%0], [%1], 16, %2;"
                 :: "r"(dst), "l"(src), "r"(srcsize));
}

__device__ __forceinline__ void ldm4(uint32_t* r, uint32_t addr) {
    asm volatile("ldmatrix.sync.aligned.m8n8.x4.shared.b16 {%0,%1,%2,%3}, [%4];"
                 : "=r"(r[0]), "=r"(r[1]), "=r"(r[2]), "=r"(r[3]) : "r"(addr));
}

__device__ __forceinline__ void mma16816(float* c, const uint32_t* a, const uint32_t* b) {
    asm("mma.sync.aligned.m16n8k16.row.col.f32.bf16.bf16.f32 "
        "{%0,%1,%2,%3}, {%4,%5,%6,%7}, {%8,%9}, {%0,%1,%2,%3};"
        : "+f"(c[0]), "+f"(c[1]), "+f"(c[2]), "+f"(c[3])
        : "r"(a[0]), "r"(a[1]), "r"(a[2]), "r"(a[3]), "r"(b[0]), "r"(b[1]));
}

template<int LAYER>
__global__ void __launch_bounds__(256, 2)
k_gemm_mma() {
    extern __shared__ char smem[];
    uint32_t sb;
    { uint64_t tmp; asm("cvta.to.shared.u64 %0, %1;" : "=l"(tmp) : "l"(smem)); sb = (uint32_t)tmp; }

    const int t = threadIdx.x;
    const int wid = t >> 5;
    const int lid = t & 31;
    const int row0 = blockIdx.x * 128;
    const int warp_m = wid & 3;
    const int warp_n = wid >> 2;

    const __nv_bfloat16* Whi = (LAYER == 1) ? g_W1hi : g_W2hi;
    const __nv_bfloat16* Wlo = (LAYER == 1) ? g_W1lo : g_W2lo;
    __nv_bfloat16* dst = (LAYER == 1) ? g_bufA1 : g_bufA2;

    // ---- stage: one commit group per K-chunk ----
    #pragma unroll
    for (int c = 0; c < 2; c++) {
        #pragma unroll
        for (int i = 0; i < 4; i++) {            // A chunk c (16KB)
            int id = t + i * 256;
            int r  = id >> 3;
            int q  = id & 7;
            int grow = row0 + r;
            const void* g = g_Ahi + (size_t)grow * D + c * 64 + q * 8;
            cp16(sb + S_AHI + c * 16384 + SWZ((uint32_t)(r * 128 + q * 16)),
                 g, (grow < NN) ? 16 : 0);
        }
        #pragma unroll
        for (int arr = 0; arr < 2; arr++) {      // Bhi, Blo chunk c (16KB each)
            const __nv_bfloat16* Bsrc = arr ? Wlo : Whi;
            const uint32_t bbase = sb + (arr ? S_BLO : S_BHI);
            #pragma unroll
            for (int i = 0; i < 4; i++) {
                int id = t + i * 256;
                int n  = id >> 3;
                int q  = id & 7;
                cp16(bbase + c * 16384 + SWZ((uint32_t)(n * 128 + q * 16)),
                     Bsrc + n * D + c * 64 + q * 8, 16);
            }
        }
        asm volatile("cp.async.commit_group;");
    }

    float acc[2][8][4];
    #pragma unroll
    for (int i = 0; i < 2; i++)
        #pragma unroll
        for (int j = 0; j < 8; j++)
            #pragma unroll
            for (int q = 0; q < 4; q++) acc[i][j][q] = 0.0f;

    // ---- compute chunk 0 while chunk 1 is still in flight ----
    #pragma unroll
    for (int c = 0; c < 2; c++) {
        if (c == 0)
            asm volatile("cp.async.wait_group 1;" ::: "memory");
        else
            asm volatile("cp.async.wait_group 0;" ::: "memory");
        __syncthreads();

        const uint32_t co = c * 16384;
        #pragma unroll
        for (int ks = 0; ks < 4; ks++) {
            uint32_t ah[2][4];
            #pragma unroll
            for (int mt = 0; mt < 2; mt++) {
                uint32_t off = SWZ((uint32_t)((warp_m * 32 + mt * 16 + (lid & 15)) * 128
                                              + ks * 32 + (lid >> 4) * 16));
                ldm4(ah[mt], sb + S_AHI + co + off);
            }
            uint32_t bh[8][2], bl[8][2];
            #pragma unroll
            for (int ntp = 0; ntp < 4; ntp++) {
                uint32_t nrow = (lid & 7) + ((lid >> 4) & 1) * 8;
                uint32_t kb = ((lid >> 3) & 1) * 16;
                uint32_t off = SWZ((uint32_t)((warp_n * 64 + ntp * 16 + nrow) * 128
                                              + ks * 32 + kb));
                uint32_t r[4];
                ldm4(r, sb + S_BHI + co + off);
                bh[2 * ntp][0] = r[0]; bh[2 * ntp][1] = r[1];
                bh[2 * ntp + 1][0] = r[2]; bh[2 * ntp + 1][1] = r[3];
                ldm4(r, sb + S_BLO + co + off);
                bl[2 * ntp][0] = r[0]; bl[2 * ntp][1] = r[1];
                bl[2 * ntp + 1][0] = r[2]; bl[2 * ntp + 1][1] = r[3];
            }
            #pragma unroll
            for (int mt = 0; mt < 2; mt++)
                #pragma unroll
                for (int nt = 0; nt < 8; nt++) {
                    mma16816(acc[mt][nt], ah[mt], bh[nt]);
                    mma16816(acc[mt][nt], ah[mt], bl[nt]);
                }
        }
    }

    const int g = lid >> 2, tig = lid & 3;
    #pragma unroll
    for (int mt = 0; mt < 2; mt++) {
        int m0 = row0 + warp_m * 32 + mt * 16 + g;
        int m8 = m0 + 8;
        float dv0 = (m0 < NN) ? g_dinv[m0] : 0.f;
        float dv8 = (m8 < NN) ? g_dinv[m8] : 0.f;
        #pragma unroll
        for (int nt = 0; nt < 8; nt++) {
            int col = warp_n * 64 + nt * 8 + tig * 2;
            if (m0 < NN)
                *reinterpret_cast<uint32_t*>(dst + m0 * D + col) =
                    pack_bf2(acc[mt][nt][0] * dv0, acc[mt][nt][1] * dv0);
            if (m8 < NN)
                *reinterpret_cast<uint32_t*>(dst + m8 * D + col) =
                    pack_bf2(acc[mt][nt][2] * dv8, acc[mt][nt][3] * dv8);
        }
    }
}

// ---------------------------------------------------------------------------
// CSR gather over bf16 messages; shift/mask unpack. Warp per node.
// LAYER 1: reads g_bufA1, writes g_Ahi (+b1,relu).  LAYER 2: pools (+b2,relu).
#define BF_ACC4(u0, u1) \
    acc0 += __uint_as_float((u0) << 16);        \
    acc1 += __uint_as_float((u0) & 0xFFFF0000u);\
    acc2 += __uint_as_float((u1) << 16);        \
    acc3 += __uint_as_float((u1) & 0xFFFF0000u);

template<int LAYER>
__global__ void __launch_bounds__(256)
k_aggr(const int* __restrict__ batch, const float* __restrict__ bin) {
    int w = (blockIdx.x * blockDim.x + threadIdx.x) >> 5;
    int lane = threadIdx.x & 31;
    if (w >= NN) return;
    const int n = w;

    const uint2* src = reinterpret_cast<const uint2*>(LAYER == 1 ? g_bufA1 : g_bufA2);
    float acc0, acc1, acc2, acc3;
    {
        uint2 u = src[n * 32 + lane];
        acc0 = __uint_as_float(u.x << 16);
        acc1 = __uint_as_float(u.x & 0xFFFF0000u);
        acc2 = __uint_as_float(u.y << 16);
        acc3 = __uint_as_float(u.y & 0xFFFF0000u);
    }
    int beg = g_rowptr[n];
    int end = g_rowptr[n + 1];

    for (int base = beg; base < end; base += 32) {
        int idx = base + lane;
        int s_l = (idx < end) ? g_csr[idx] : 0;
        int cnt = min(32, end - base);
        int j = 0;
        for (; j + 4 <= cnt; j += 4) {
            int s0 = __shfl_sync(0xffffffffu, s_l, j);
            int s1 = __shfl_sync(0xffffffffu, s_l, j + 1);
            int s2 = __shfl_sync(0xffffffffu, s_l, j + 2);
            int s3 = __shfl_sync(0xffffffffu, s_l, j + 3);
            uint2 u0 = src[s0 * 32 + lane];
            uint2 u1 = src[s1 * 32 + lane];
            uint2 u2 = src[s2 * 32 + lane];
            uint2 u3 = src[s3 * 32 + lane];
            BF_ACC4(u0.x, u0.y)
            BF_ACC4(u1.x, u1.y)
            BF_ACC4(u2.x, u2.y)
            BF_ACC4(u3.x, u3.y)
        }
        for (; j < cnt; j++) {
            int s = __shfl_sync(0xffffffffu, s_l, j);
            uint2 u = src[s * 32 + lane];
            BF_ACC4(u.x, u.y)
        }
    }

    float dv = g_dinv[n];
    float4 bb = reinterpret_cast<const float4*>(bin)[lane];
    float r0 = fmaxf(fmaf(dv, acc0, bb.x), 0.f);
    float r1 = fmaxf(fmaf(dv, acc1, bb.y), 0.f);
    float r2 = fmaxf(fmaf(dv, acc2, bb.z), 0.f);
    float r3 = fmaxf(fmaf(dv, acc3, bb.w), 0.f);

    if (LAYER == 1) {
        reinterpret_cast<uint2*>(g_Ahi)[n * 32 + lane] =
            make_uint2(pack_bf2(r0, r1), pack_bf2(r2, r3));
    } else {
        int g = batch[n];
        red_add_v4(g_pool + g * D + lane * 4, make_float4(r0, r1, r2, r3));
    }
}

// ---------------------------------------------------------------------------
__global__ void k_final(const float* __restrict__ Wl,
                        const float* __restrict__ bl,
                        float* __restrict__ out) {
    __shared__ float p[D];
    int g = blockIdx.x;
    int o = threadIdx.x;
    p[o]      = g_pool[g * D + o];
    p[o + 64] = g_pool[g * D + o + 64];
    g_pool[g * D + o]      = 0.0f;   // self-clean for next replay
    g_pool[g * D + o + 64] = 0.0f;
    __syncthreads();
    float acc = bl[o];
    #pragma unroll 8
    for (int c = 0; c < D; c++)
        acc = fmaf(p[c], Wl[c * OD + o], acc);
    out[g * OD + o] = acc;
}

// ---------------------------------------------------------------------------
extern "C" void kernel_launch(void* const* d_in, const int* in_sizes, int n_in,
                              void* d_out, int out_size) {
    const float* x     = (const float*)d_in[0];
    const int*   ei    = (const int*)d_in[1];      // int32 (JAX x64 disabled)
    const int*   batch = (const int*)d_in[2];
    const float* W1    = (const float*)d_in[3];
    const float* b1    = (const float*)d_in[4];
    const float* W2    = (const float*)d_in[5];
    const float* b2    = (const float*)d_in[6];
    const float* Wl    = (const float*)d_in[7];
    const float* bl    = (const float*)d_in[8];
    float* out = (float*)d_out;

    cudaFuncSetAttribute(k_gemm_mma<1>,
                         cudaFuncAttributeMaxDynamicSharedMemorySize, GEMM_SMEM);
    cudaFuncSetAttribute(k_gemm_mma<2>,
                         cudaFuncAttributeMaxDynamicSharedMemorySize, GEMM_SMEM);

    cudaStream_t side;
    cudaStreamCreateWithFlags(&side, cudaStreamNonBlocking);
    cudaEvent_t e0, e1, e2;
    cudaEventCreateWithFlags(&e0, cudaEventDisableTiming);
    cudaEventCreateWithFlags(&e1, cudaEventDisableTiming);
    cudaEventCreateWithFlags(&e2, cudaEventDisableTiming);

    // Fork: side stream does dense prep concurrent with CSR build.
    cudaEventRecord(e0, 0);
    cudaStreamWaitEvent(side, e0, 0);
    k_prepxw<<<NB_PREPX + NB_PREPW, 256, 0, side>>>(x, W1, W2);

    // CSR chain on main stream (single-pass lookback scan)
    k_count<<<(EE + 255) / 256, 256>>>(ei);
    k_scan<<<NBLK, SCAN_BLK>>>();
    cudaEventRecord(e1, 0);

    // GEMM1 on side (needs prepxw + dinv), concurrent with fill on main
    cudaStreamWaitEvent(side, e1, 0);
    k_gemm_mma<1><<<(NN + 127) / 128, 256, GEMM_SMEM, side>>>();
    cudaEventRecord(e2, side);

    k_fill<<<(EE + 255) / 256, 256>>>(ei);

    // Join, then linear: aggr1 -> GEMM2 -> aggr2 -> head
    cudaStreamWaitEvent(0, e2, 0);
    k_aggr<1><<<(NN * 32 + 255) / 256, 256>>>(nullptr, b1);
    k_gemm_mma<2><<<(NN + 127) / 128, 256, GEMM_SMEM>>>();
    k_aggr<2><<<(NN * 32 + 255) / 256, 256>>>(batch, b2);
    k_final<<<NG, OD>>>(Wl, bl, out);

    cudaEventDestroy(e0);
    cudaEventDestroy(e1);
    cudaEventDestroy(e2);
    cudaStreamDestroy(side);
}